// round 16
// baseline (speedup 1.0000x reference)
#include <cuda_runtime.h>
#include <cuda_bf16.h>
#include <math.h>
#include <stdint.h>

#define NB 4
#define SQ 2048
#define HD 512
#define BSH (NB * SQ * HD)
#define KSCALE 0.044194173824159216f
#define TB 10240            // one tile: 128 rows * 80 bytes
#define STG (4 * TB)        // 4 tiles per stage
#define SMEM_BYTES (2 * STG)

typedef __nv_bfloat16 bf16;
struct __align__(8) bf4 { __nv_bfloat162 a, b; };

// ---- scratch ----
__device__ float g_sf[2][BSH];
__device__ bf16  g_sh[2][BSH], g_sl[2][BSH];
__device__ bf16  g_xh[BSH], g_xl[BSH];
__device__ bf16  g_kh[BSH], g_kl[BSH];
__device__ bf16  g_kth[BSH], g_ktl[BSH];
__device__ bf16  g_vth[BSH], g_vtl[BSH];
__device__ bf16  g_ath[BSH], g_atl[BSH];
__device__ bf16  g_wh[4 * HD * HD], g_wl[4 * HD * HD];
__device__ float g_tmpf[BSH];
__device__ float g_scores[(size_t)NB * SQ * SQ];
__device__ bf16  g_ph[(size_t)NB * SQ * SQ], g_pl[(size_t)NB * SQ * SQ];
__device__ int   g_converged, g_iters, g_sel, g_ctr;
__device__ int   g_smctr[64];
__device__ float g_sumd, g_sumn;

// ---- helpers ----
__device__ __forceinline__ uint32_t smem_u32(const void* p) {
    uint32_t a;
    asm("{ .reg .u64 t; cvta.to.shared.u64 t, %1; cvt.u32.u64 %0, t; }" : "=r"(a) : "l"(p));
    return a;
}
__device__ __forceinline__ void ldsm4(uint32_t* r, uint32_t addr) {
    asm("ldmatrix.sync.aligned.m8n8.x4.shared.b16 {%0,%1,%2,%3}, [%4];"
        : "=r"(r[0]), "=r"(r[1]), "=r"(r[2]), "=r"(r[3]) : "r"(addr) : "memory");
}
__device__ __forceinline__ void mma16816(float* d, const uint32_t* a, const uint32_t* b) {
    asm("mma.sync.aligned.m16n8k16.row.col.f32.bf16.bf16.f32 "
        "{%0,%1,%2,%3}, {%4,%5,%6,%7}, {%8,%9}, {%0,%1,%2,%3};"
        : "+f"(d[0]), "+f"(d[1]), "+f"(d[2]), "+f"(d[3])
        : "r"(a[0]), "r"(a[1]), "r"(a[2]), "r"(a[3]), "r"(b[0]), "r"(b[1]));
}
__device__ __forceinline__ void cpa16(uint32_t s, const void* g) {
    asm volatile("cp.async.cg.shared.global [%0], [%1], 16;" :: "r"(s), "l"(g));
}
__device__ __forceinline__ void split2(float v, bf16& h, bf16& l) {
    h = __float2bfloat16(v);
    l = __float2bfloat16(v - __bfloat162float(h));
}

// ---- control ----
__global__ void k_init() {
    g_converged = 0; g_iters = 0; g_sel = 0; g_ctr = 0;
    g_sumd = 0.0f; g_sumn = 0.0f;
    for (int i = 0; i < 64; i++) g_smctr[i] = 0;
}
__global__ void k_tail(float* out, int extra) {
    if (extra >= 1) out[BSH] = (float)g_iters;
    if (extra >= 2) out[BSH + 1] = g_converged ? 1.0f : 0.0f;
}

// ---- fused fp32 -> (hi,lo) bf16 for x + 4 weights ----
__global__ void k_cvt_all(const float* __restrict__ x,
                          const float* __restrict__ Wq, const float* __restrict__ Wk,
                          const float* __restrict__ Wv, const float* __restrict__ Wo) {
    const int nwb = (HD * HD) / 1024;
    int b = blockIdx.x;
    const float* src;
    bf16 *h, *l;
    int base;
    if (b < BSH / 1024) {
        src = x; h = g_xh; l = g_xl; base = b * 1024;
    } else {
        int wb = b - BSH / 1024;
        int wi = wb / nwb;
        base = (wb - wi * nwb) * 1024;
        src = (wi == 0) ? Wq : (wi == 1) ? Wk : (wi == 2) ? Wv : Wo;
        h = g_wh + wi * HD * HD; l = g_wl + wi * HD * HD;
    }
    int i = base + threadIdx.x * 4;
    float4 v = *(const float4*)(src + i);
    bf4 hv, lv;
    split2(v.x, hv.a.x, lv.a.x);
    split2(v.y, hv.a.y, lv.a.y);
    split2(v.z, hv.b.x, lv.b.x);
    split2(v.w, hv.b.y, lv.b.y);
    *(bf4*)(h + i) = hv;
    *(bf4*)(l + i) = lv;
}

// ---- transpose-convert fp32 [B,S,H] -> bf16 hi/lo [B,H,S], K and V in one launch ----
__global__ void k_tcvt2(const float* __restrict__ srcK, const float* __restrict__ srcV) {
    __shared__ float t[32][33];
    const int zz = blockIdx.z;
    const int z = zz & 3;
    const float* s = ((zz < 4) ? srcK : srcV) + (size_t)z * SQ * HD;
    bf16* th = (zz < 4) ? g_kth : g_vth;
    bf16* tl = (zz < 4) ? g_ktl : g_vtl;
    const int h0 = blockIdx.x * 32, s0 = blockIdx.y * 32;
    const int tx = threadIdx.x, ty = threadIdx.y;
    for (int r = ty; r < 32; r += 8) t[r][tx] = s[(size_t)(s0 + r) * HD + h0 + tx];
    __syncthreads();
    for (int r = ty; r < 32; r += 8) {
        float v = t[tx][r];
        size_t o = (size_t)z * HD * SQ + (size_t)(h0 + r) * SQ + s0 + tx;
        bf16 hh, ll;
        split2(v, hh, ll);
        th[o] = hh;
        tl[o] = ll;
    }
}

// ---- cp.async one 128x32 bf16 tile into smem (row stride 80B), 128 threads ----
__device__ __forceinline__ void cpa_tile(uint32_t sdst, const bf16* __restrict__ src,
                                         size_t row0, int k0, int ld, int tid) {
#pragma unroll
    for (int r = 0; r < 4; r++) {
        int seg = tid + r * 128;          // 0..511
        int row = seg >> 2, sc = seg & 3; // row 0..127
        cpa16(sdst + row * 80 + sc * 16,
              src + (row0 + row) * (size_t)ld + k0 + sc * 8);
    }
}

// ---- split-bf16 HMMA GEMM: C[128,128] = A[128,K] @ B[128,K]^T (all K-major) ----
// 128 threads, 4 warps in 2x2, each warp 64x64; all fragments loaded up-front per k16
// dosm: last CTA per scores row-block runs the row softmax inline (counter pattern)
// cm:   last AV CTA runs convergence finalize on-device
__global__ void __launch_bounds__(128, 2)
k_gemm(const bf16* __restrict__ Ah_, const bf16* __restrict__ Al_,
       const bf16* __restrict__ Bh_, const bf16* __restrict__ Bl_,
       float* Cf, bf16* Ch, bf16* Cl,
       const float* bias, const float* bias_k, const float* bias_v,
       float scale, int Ktot, int ldc,
       size_t aB, size_t bB, size_t cB, int am, int cm, int guard, int qkv, int dosm) {
    const bool skip = (guard && g_converged);
    if (skip && !cm) return;
    extern __shared__ char smem[];
    const int tid = threadIdx.x, lane = tid & 31, w = tid >> 5;

    if (!skip) {
        const uint32_t sb = smem_u32(smem);
        const int warp_m = (w & 1) * 64, warp_n = (w >> 1) * 64;

        const int z = blockIdx.z;
        const bf16 *Ah = Ah_, *Al = Al_;
        if (am) { int s = g_sel; Ah = g_sh[s]; Al = g_sl[s]; }
        Ah += (size_t)z * aB; Al += (size_t)z * aB;
        const bf16* Bh = Bh_ + (size_t)z * bB;
        const bf16* Bl = Bl_ + (size_t)z * bB;
        const float* Cold = nullptr;
        if (cm) {
            int s = g_sel ^ 1;
            Cf = g_sf[s]; Ch = g_sh[s]; Cl = g_sl[s];
            Cold = g_sf[s ^ 1] + (size_t)z * cB;
        }
        size_t nrow0 = (size_t)blockIdx.x * 128;
        int n0 = blockIdx.x * 128;
        if (qkv) {
            const int nw = HD * HD;
            int wi = blockIdx.x >> 2, bxl = blockIdx.x & 3;
            Bh = g_wh + wi * nw; Bl = g_wl + wi * nw;
            bias = (wi == 0) ? bias : (wi == 1) ? bias_k : bias_v;
            if (wi == 0)      { Cf = g_sf[0]; Ch = g_sh[0]; Cl = g_sl[0]; }
            else if (wi == 1) { Cf = g_tmpf;  Ch = g_kh;    Cl = g_kl;    }
            else              { Cf = g_scores; Ch = nullptr; Cl = nullptr; }
            nrow0 = (size_t)bxl * 128; n0 = bxl * 128;
        }
        if (Cf) Cf += (size_t)z * cB;
        if (Ch) { Ch += (size_t)z * cB; Cl += (size_t)z * cB; }

        const size_t row0 = (size_t)blockIdx.y * 128;

        uint32_t offA[4], offB[4];
#pragma unroll
        for (int mt = 0; mt < 4; mt++)
            offA[mt] = (uint32_t)(warp_m + mt * 16 + (lane & 7) + 8 * ((lane >> 3) & 1)) * 80
                     + (uint32_t)(lane >> 4) * 16;
#pragma unroll
        for (int p = 0; p < 4; p++)
            offB[p] = (uint32_t)(warp_n + p * 16 + (lane & 7) + 8 * (lane >> 4)) * 80
                    + (uint32_t)((lane >> 3) & 1) * 16;

        float acc[4][8][4];
#pragma unroll
        for (int mt = 0; mt < 4; mt++)
#pragma unroll
            for (int nt = 0; nt < 8; nt++)
#pragma unroll
                for (int i = 0; i < 4; i++) acc[mt][nt][i] = 0.0f;

        const int nch = Ktot >> 5;
        cpa_tile(sb,          Ah, row0,  0, Ktot, tid);
        cpa_tile(sb + TB,     Al, row0,  0, Ktot, tid);
        cpa_tile(sb + 2 * TB, Bh, nrow0, 0, Ktot, tid);
        cpa_tile(sb + 3 * TB, Bl, nrow0, 0, Ktot, tid);
        asm volatile("cp.async.commit_group;");

        for (int c = 0; c < nch; c++) {
            if (c + 1 < nch) {
                uint32_t s2 = sb + ((c + 1) & 1) * STG;
                int k0 = (c + 1) << 5;
                cpa_tile(s2,          Ah, row0,  k0, Ktot, tid);
                cpa_tile(s2 + TB,     Al, row0,  k0, Ktot, tid);
                cpa_tile(s2 + 2 * TB, Bh, nrow0, k0, Ktot, tid);
                cpa_tile(s2 + 3 * TB, Bl, nrow0, k0, Ktot, tid);
                asm volatile("cp.async.commit_group;");
                asm volatile("cp.async.wait_group 1;");
            } else {
                asm volatile("cp.async.wait_group 0;");
            }
            __syncthreads();

            const uint32_t ss = sb + (c & 1) * STG;
#pragma unroll
            for (int k16 = 0; k16 < 2; k16++) {
                const uint32_t kof = k16 * 32;
                uint32_t ah[4][4], al[4][4], bh[4][4], bl[4][4];
#pragma unroll
                for (int mt = 0; mt < 4; mt++) {
                    ldsm4(ah[mt], ss + offA[mt] + kof);
                    ldsm4(al[mt], ss + TB + offA[mt] + kof);
                }
#pragma unroll
                for (int p = 0; p < 4; p++) {
                    ldsm4(bh[p], ss + 2 * TB + offB[p] + kof);
                    ldsm4(bl[p], ss + 3 * TB + offB[p] + kof);
                }
#pragma unroll
                for (int p = 0; p < 4; p++) {
#pragma unroll
                    for (int sub = 0; sub < 2; sub++) {
                        const uint32_t* pbh = &bh[p][sub * 2];
                        const uint32_t* pbl = &bl[p][sub * 2];
                        int nt = p * 2 + sub;
#pragma unroll
                        for (int mt = 0; mt < 4; mt++) {
                            mma16816(acc[mt][nt], ah[mt], pbh);
                            mma16816(acc[mt][nt], ah[mt], pbl);
                            mma16816(acc[mt][nt], al[mt], pbh);
                        }
                    }
                }
            }
            __syncthreads();
        }

        // epilogue (+ fused Frobenius-delta partials when writing state)
        float sd = 0.0f, sn = 0.0f;
        const int cr = lane >> 2, cc = (lane & 3) * 2;
#pragma unroll
        for (int mt = 0; mt < 4; mt++) {
#pragma unroll
            for (int nt = 0; nt < 8; nt++) {
#pragma unroll
                for (int half = 0; half < 2; half++) {
                    int row = warp_m + mt * 16 + cr + half * 8;
                    int col = warp_n + nt * 8 + cc;
                    float vx = acc[mt][nt][half * 2 + 0] * scale;
                    float vy = acc[mt][nt][half * 2 + 1] * scale;
                    int gc = n0 + col;
                    if (bias) { vx += __ldg(bias + gc); vy += __ldg(bias + gc + 1); }
                    size_t ci = (row0 + row) * (size_t)ldc + gc;
                    if (Cf) { float2 o; o.x = vx; o.y = vy; *(float2*)(Cf + ci) = o; }
                    if (Cold) {
                        float2 ov = *(const float2*)(Cold + ci);
                        float dx = vx - ov.x, dy = vy - ov.y;
                        sd += dx * dx + dy * dy;
                        sn += ov.x * ov.x + ov.y * ov.y;
                    }
                    if (Ch) {
                        __nv_bfloat162 hv, lv;
                        split2(vx, hv.x, lv.x);
                        split2(vy, hv.y, lv.y);
                        *(__nv_bfloat162*)(Ch + ci) = hv;
                        *(__nv_bfloat162*)(Cl + ci) = lv;
                    }
                }
            }
        }
        if (Cold) {
#pragma unroll
            for (int o = 16; o; o >>= 1) {
                sd += __shfl_xor_sync(0xffffffffu, sd, o);
                sn += __shfl_xor_sync(0xffffffffu, sn, o);
            }
            float* rbuf = (float*)smem;
            __syncthreads();
            if (lane == 0) { rbuf[w] = sd; rbuf[4 + w] = sn; }
            __syncthreads();
            if (tid == 0) {
                float t1 = 0.0f, t2 = 0.0f;
#pragma unroll
                for (int i = 0; i < 4; i++) { t1 += rbuf[i]; t2 += rbuf[4 + i]; }
                atomicAdd(&g_sumd, t1);
                atomicAdd(&g_sumn, t2);
            }
        }

        // fused row softmax: last finishing CTA of each (y,z) row-block does
        // softmax over rows [row0, row0+128) and emits bf16 hi/lo probs.
        if (dosm) {
            __shared__ int smlast;
            __threadfence();
            __syncthreads();
            if (tid == 0) {
                int idx = blockIdx.z * 16 + blockIdx.y;
                smlast = (atomicAdd(&g_smctr[idx], 1) == 15) ? 1 : 0;
            }
            __syncthreads();
            if (smlast) {
                const size_t SS = (size_t)SQ * SQ;
                const size_t rbase = (size_t)blockIdx.z * SS + row0 * SQ;
                for (int r = w; r < 128; r += 4) {
                    const float4* rp = (const float4*)(g_scores + rbase + (size_t)r * SQ);
                    float4 v[16];
                    float m = -3.4e38f;
#pragma unroll
                    for (int i = 0; i < 16; i++) {
                        v[i] = rp[lane + 32 * i];
                        m = fmaxf(m, fmaxf(fmaxf(v[i].x, v[i].y), fmaxf(v[i].z, v[i].w)));
                    }
#pragma unroll
                    for (int o = 16; o; o >>= 1) m = fmaxf(m, __shfl_xor_sync(0xffffffffu, m, o));
                    float s = 0.0f;
#pragma unroll
                    for (int i = 0; i < 16; i++) {
                        v[i].x = __expf(v[i].x - m); s += v[i].x;
                        v[i].y = __expf(v[i].y - m); s += v[i].y;
                        v[i].z = __expf(v[i].z - m); s += v[i].z;
                        v[i].w = __expf(v[i].w - m); s += v[i].w;
                    }
#pragma unroll
                    for (int o = 16; o; o >>= 1) s += __shfl_xor_sync(0xffffffffu, s, o);
                    const float inv = 1.0f / s;
                    bf4* ph4 = (bf4*)(g_ph + rbase + (size_t)r * SQ);
                    bf4* pl4 = (bf4*)(g_pl + rbase + (size_t)r * SQ);
#pragma unroll
                    for (int i = 0; i < 16; i++) {
                        bf4 hv, lv;
                        split2(v[i].x * inv, hv.a.x, lv.a.x);
                        split2(v[i].y * inv, hv.a.y, lv.a.y);
                        split2(v[i].z * inv, hv.b.x, lv.b.x);
                        split2(v[i].w * inv, hv.b.y, lv.b.y);
                        ph4[lane + 32 * i] = hv;
                        pl4[lane + 32 * i] = lv;
                    }
                }
                if (tid == 0) g_smctr[blockIdx.z * 16 + blockIdx.y] = 0;
            }
        }
    }

    // device-side finalize: last AV CTA computes delta, updates control state
    if (cm && tid == 0) {
        __threadfence();
        int ntiles = (int)(gridDim.x * gridDim.y * gridDim.z);
        int done = atomicAdd(&g_ctr, 1);
        if (done == ntiles - 1) {
            if (!g_converged) {
                float sumd = atomicAdd(&g_sumd, 0.0f);
                float sumn = atomicAdd(&g_sumn, 0.0f);
                float delta = sqrtf(sumd) / (sqrtf(sumn) + 1e-8f);
                g_iters += 1;
                if (delta < 1e-4f) g_converged = 1;
                g_sel ^= 1;
            }
            g_sumd = 0.0f; g_sumn = 0.0f;
            g_ctr = 0;
            __threadfence();
        }
    }
}

// ---- launch ----
extern "C" void kernel_launch(void* const* d_in, const int* in_sizes, int n_in,
                              void* d_out, int out_size) {
    const float* x  = (const float*)d_in[0];
    const float* Wq = (const float*)d_in[1];
    const float* bq = (const float*)d_in[2];
    const float* Wk = (const float*)d_in[3];
    const float* bk = (const float*)d_in[4];
    const float* Wv = (const float*)d_in[5];
    const float* bv = (const float*)d_in[6];
    const float* Wo = (const float*)d_in[7];
    const float* bo = (const float*)d_in[8];
    float* out = (float*)d_out;

    void* pv;
    cudaGetSymbolAddress(&pv, g_xh);   bf16* xh = (bf16*)pv;
    cudaGetSymbolAddress(&pv, g_xl);   bf16* xl = (bf16*)pv;
    cudaGetSymbolAddress(&pv, g_kh);   bf16* kh = (bf16*)pv;
    cudaGetSymbolAddress(&pv, g_kl);   bf16* kl = (bf16*)pv;
    cudaGetSymbolAddress(&pv, g_kth);  bf16* kth = (bf16*)pv;
    cudaGetSymbolAddress(&pv, g_ktl);  bf16* ktl = (bf16*)pv;
    cudaGetSymbolAddress(&pv, g_vth);  bf16* vth = (bf16*)pv;
    cudaGetSymbolAddress(&pv, g_vtl);  bf16* vtl = (bf16*)pv;
    cudaGetSymbolAddress(&pv, g_ath);  bf16* ath = (bf16*)pv;
    cudaGetSymbolAddress(&pv, g_atl);  bf16* atl = (bf16*)pv;
    cudaGetSymbolAddress(&pv, g_wh);   bf16* wh = (bf16*)pv;
    cudaGetSymbolAddress(&pv, g_wl);   bf16* wl = (bf16*)pv;
    cudaGetSymbolAddress(&pv, g_tmpf); float* tmpf = (float*)pv;
    cudaGetSymbolAddress(&pv, g_scores); float* sc = (float*)pv;
    cudaGetSymbolAddress(&pv, g_ph);   bf16* ph = (bf16*)pv;
    cudaGetSymbolAddress(&pv, g_pl);   bf16* pl = (bf16*)pv;

    cudaFuncSetAttribute(k_gemm, cudaFuncAttributeMaxDynamicSharedMemorySize, SMEM_BYTES);

    const int nw = HD * HD;
    const dim3 gQKV(12, 64, 1);   // fused q/k/v projections: 8192 x 1536
    const dim3 gP(4, 64, 1);
    const dim3 gS(16, 16, 4);
    const dim3 gV(4, 16, 4);
    const dim3 gT2(16, 64, 8);    // merged K+V transpose
    const dim3 bT(32, 8);
    const size_t aS = (size_t)SQ * HD, cS = (size_t)SQ * SQ;

    k_init<<<1, 1>>>();
    k_cvt_all<<<BSH / 1024 + 4 * (nw / 1024), 256>>>(x, Wq, Wk, Wv, Wo);

    // fused QKV: q -> state0 (f+h+l)+bq, k -> tmpf+kh/kl+bk, v -> scores scratch+bv
    k_gemm<<<gQKV, 128, SMEM_BYTES>>>(xh, xl, nullptr, nullptr,
                                      nullptr, nullptr, nullptr,
                                      bq, bk, bv, 1.0f,
                                      HD, HD, 0, 0, 0, 0, 0, 0, 1, 0);
    // merged transpose-convert of K (from tmpf) and V (from scores scratch)
    k_tcvt2<<<gT2, bT>>>(tmpf, sc);

    for (int it = 0; it < 5; it++) {
        // scores GEMM with fused row softmax (dosm=1)
        k_gemm<<<gS, 128, SMEM_BYTES>>>(nullptr, nullptr, kh, kl, sc, nullptr, nullptr,
                                        nullptr, nullptr, nullptr, KSCALE,
                                        HD, SQ, aS, aS, cS, 1, 0, 1, 0, 1);
        // AV with on-device finalize (cm=1)
        k_gemm<<<gV, 128, SMEM_BYTES>>>(ph, pl, kth, ktl, nullptr, nullptr, nullptr,
                                        nullptr, nullptr, nullptr, 1.0f,
                                        SQ, HD, cS, aS, aS, 0, 1, 1, 0, 0);
    }

    // readout: scores + fused softmax vs keys, AV vs values, then output projection
    k_gemm<<<gS, 128, SMEM_BYTES>>>(nullptr, nullptr, kh, kl, sc, nullptr, nullptr,
                                    nullptr, nullptr, nullptr, KSCALE,
                                    HD, SQ, aS, aS, cS, 1, 0, 0, 0, 1);
    k_gemm<<<gV, 128, SMEM_BYTES>>>(ph, pl, vth, vtl, nullptr, ath, atl,
                                    nullptr, nullptr, nullptr, 1.0f,
                                    SQ, HD, cS, aS, aS, 0, 0, 0, 0, 0);
    k_gemm<<<gP, 128, SMEM_BYTES>>>(ath, atl, wh + 3 * nw, wl + 3 * nw, out, nullptr, nullptr,
                                    bo, nullptr, nullptr, 1.0f,
                                    HD, HD, 0, 0, 0, 0, 0, 0, 0, 0);

    if (out_size > BSH) k_tail<<<1, 1>>>(out, out_size - BSH);
}

// round 17
// speedup vs baseline: 1.1626x; 1.1626x over previous
#include <cuda_runtime.h>
#include <cuda_bf16.h>
#include <math.h>
#include <stdint.h>

#define NB 4
#define SQ 2048
#define HD 512
#define BSH (NB * SQ * HD)
#define KSCALE 0.044194173824159216f
#define TB 10240            // one tile: 128 rows * 80 bytes
#define STG (4 * TB)        // 4 tiles per stage
#define SMEM_BYTES (2 * STG)

typedef __nv_bfloat16 bf16;
struct __align__(8) bf4 { __nv_bfloat162 a, b; };

// ---- scratch ----
__device__ float g_sf[2][BSH];
__device__ bf16  g_sh[2][BSH], g_sl[2][BSH];
__device__ bf16  g_xh[BSH], g_xl[BSH];
__device__ bf16  g_kh[BSH], g_kl[BSH];
__device__ bf16  g_kth[BSH], g_ktl[BSH];
__device__ bf16  g_vth[BSH], g_vtl[BSH];
__device__ bf16  g_ath[BSH], g_atl[BSH];
__device__ bf16  g_wh[4 * HD * HD], g_wl[4 * HD * HD];
__device__ float g_tmpf[BSH];
__device__ float g_scores[(size_t)NB * SQ * SQ];
__device__ bf16  g_ph[(size_t)NB * SQ * SQ], g_pl[(size_t)NB * SQ * SQ];
__device__ int   g_converged, g_iters, g_sel, g_ctr;
__device__ float g_sumd, g_sumn;

// ---- helpers ----
__device__ __forceinline__ uint32_t smem_u32(const void* p) {
    uint32_t a;
    asm("{ .reg .u64 t; cvta.to.shared.u64 t, %1; cvt.u32.u64 %0, t; }" : "=r"(a) : "l"(p));
    return a;
}
__device__ __forceinline__ void ldsm4(uint32_t* r, uint32_t addr) {
    asm("ldmatrix.sync.aligned.m8n8.x4.shared.b16 {%0,%1,%2,%3}, [%4];"
        : "=r"(r[0]), "=r"(r[1]), "=r"(r[2]), "=r"(r[3]) : "r"(addr) : "memory");
}
__device__ __forceinline__ void mma16816(float* d, const uint32_t* a, const uint32_t* b) {
    asm("mma.sync.aligned.m16n8k16.row.col.f32.bf16.bf16.f32 "
        "{%0,%1,%2,%3}, {%4,%5,%6,%7}, {%8,%9}, {%0,%1,%2,%3};"
        : "+f"(d[0]), "+f"(d[1]), "+f"(d[2]), "+f"(d[3])
        : "r"(a[0]), "r"(a[1]), "r"(a[2]), "r"(a[3]), "r"(b[0]), "r"(b[1]));
}
__device__ __forceinline__ void cpa16(uint32_t s, const void* g) {
    asm volatile("cp.async.cg.shared.global [%0], [%1], 16;" :: "r"(s), "l"(g));
}
__device__ __forceinline__ void split2(float v, bf16& h, bf16& l) {
    h = __float2bfloat16(v);
    l = __float2bfloat16(v - __bfloat162float(h));
}

// ---- control ----
__global__ void k_init() {
    g_converged = 0; g_iters = 0; g_sel = 0; g_ctr = 0;
    g_sumd = 0.0f; g_sumn = 0.0f;
}
__global__ void k_tail(float* out, int extra) {
    if (extra >= 1) out[BSH] = (float)g_iters;
    if (extra >= 2) out[BSH + 1] = g_converged ? 1.0f : 0.0f;
}

// ---- fused fp32 -> (hi,lo) bf16 for x + 4 weights ----
__global__ void k_cvt_all(const float* __restrict__ x,
                          const float* __restrict__ Wq, const float* __restrict__ Wk,
                          const float* __restrict__ Wv, const float* __restrict__ Wo) {
    const int nwb = (HD * HD) / 1024;
    int b = blockIdx.x;
    const float* src;
    bf16 *h, *l;
    int base;
    if (b < BSH / 1024) {
        src = x; h = g_xh; l = g_xl; base = b * 1024;
    } else {
        int wb = b - BSH / 1024;
        int wi = wb / nwb;
        base = (wb - wi * nwb) * 1024;
        src = (wi == 0) ? Wq : (wi == 1) ? Wk : (wi == 2) ? Wv : Wo;
        h = g_wh + wi * HD * HD; l = g_wl + wi * HD * HD;
    }
    int i = base + threadIdx.x * 4;
    float4 v = *(const float4*)(src + i);
    bf4 hv, lv;
    split2(v.x, hv.a.x, lv.a.x);
    split2(v.y, hv.a.y, lv.a.y);
    split2(v.z, hv.b.x, lv.b.x);
    split2(v.w, hv.b.y, lv.b.y);
    *(bf4*)(h + i) = hv;
    *(bf4*)(l + i) = lv;
}

// ---- transpose-convert fp32 [B,S,H] -> bf16 hi/lo [B,H,S], K and V in one launch ----
__global__ void k_tcvt2(const float* __restrict__ srcK, const float* __restrict__ srcV) {
    __shared__ float t[32][33];
    const int zz = blockIdx.z;
    const int z = zz & 3;
    const float* s = ((zz < 4) ? srcK : srcV) + (size_t)z * SQ * HD;
    bf16* th = (zz < 4) ? g_kth : g_vth;
    bf16* tl = (zz < 4) ? g_ktl : g_vtl;
    const int h0 = blockIdx.x * 32, s0 = blockIdx.y * 32;
    const int tx = threadIdx.x, ty = threadIdx.y;
    for (int r = ty; r < 32; r += 8) t[r][tx] = s[(size_t)(s0 + r) * HD + h0 + tx];
    __syncthreads();
    for (int r = ty; r < 32; r += 8) {
        float v = t[tx][r];
        size_t o = (size_t)z * HD * SQ + (size_t)(h0 + r) * SQ + s0 + tx;
        bf16 hh, ll;
        split2(v, hh, ll);
        th[o] = hh;
        tl[o] = ll;
    }
}

// ---- register softmax: row of 2048, 256 threads ----
__global__ void __launch_bounds__(256)
k_softmax(int guard) {
    if (guard && g_converged) return;
    const size_t base = (size_t)blockIdx.x * SQ;
    const float4* r4 = (const float4*)(g_scores + base);
    const int tid = threadIdx.x, lane = tid & 31, w = tid >> 5;
    __shared__ float wr[16];

    float4 a = r4[tid], b = r4[tid + 256];
    float m = fmaxf(fmaxf(fmaxf(a.x, a.y), fmaxf(a.z, a.w)),
                    fmaxf(fmaxf(b.x, b.y), fmaxf(b.z, b.w)));
#pragma unroll
    for (int o = 16; o; o >>= 1) m = fmaxf(m, __shfl_xor_sync(0xffffffffu, m, o));
    if (lane == 0) wr[w] = m;
    __syncthreads();
    float mm = wr[0];
#pragma unroll
    for (int i = 1; i < 8; i++) mm = fmaxf(mm, wr[i]);

    float e[8];
    e[0] = __expf(a.x - mm); e[1] = __expf(a.y - mm);
    e[2] = __expf(a.z - mm); e[3] = __expf(a.w - mm);
    e[4] = __expf(b.x - mm); e[5] = __expf(b.y - mm);
    e[6] = __expf(b.z - mm); e[7] = __expf(b.w - mm);
    float s = e[0] + e[1] + e[2] + e[3] + e[4] + e[5] + e[6] + e[7];
#pragma unroll
    for (int o = 16; o; o >>= 1) s += __shfl_xor_sync(0xffffffffu, s, o);
    if (lane == 0) wr[8 + w] = s;
    __syncthreads();
    float tot = 0.0f;
#pragma unroll
    for (int i = 0; i < 8; i++) tot += wr[8 + i];
    const float inv = 1.0f / tot;

    bf4* ph4 = (bf4*)(g_ph + base);
    bf4* pl4 = (bf4*)(g_pl + base);
#pragma unroll
    for (int g = 0; g < 2; g++) {
        bf4 hv, lv;
        split2(e[g * 4 + 0] * inv, hv.a.x, lv.a.x);
        split2(e[g * 4 + 1] * inv, hv.a.y, lv.a.y);
        split2(e[g * 4 + 2] * inv, hv.b.x, lv.b.x);
        split2(e[g * 4 + 3] * inv, hv.b.y, lv.b.y);
        ph4[tid + g * 256] = hv;
        pl4[tid + g * 256] = lv;
    }
}

// ---- cp.async one 128x32 bf16 tile into smem (row stride 80B), 128 threads ----
__device__ __forceinline__ void cpa_tile(uint32_t sdst, const bf16* __restrict__ src,
                                         size_t row0, int k0, int ld, int tid) {
#pragma unroll
    for (int r = 0; r < 4; r++) {
        int seg = tid + r * 128;          // 0..511
        int row = seg >> 2, sc = seg & 3; // row 0..127
        cpa16(sdst + row * 80 + sc * 16,
              src + (row0 + row) * (size_t)ld + k0 + sc * 8);
    }
}

// ---- split-bf16 HMMA GEMM: C[128,128] = A[128,K] @ B[128,K]^T (all K-major) ----
// 128 threads, 4 warps in 2x2, each warp 64x64; all fragments loaded up-front per k16
__global__ void __launch_bounds__(128, 2)
k_gemm(const bf16* __restrict__ Ah_, const bf16* __restrict__ Al_,
       const bf16* __restrict__ Bh_, const bf16* __restrict__ Bl_,
       float* Cf, bf16* Ch, bf16* Cl,
       const float* bias, const float* bias_k, const float* bias_v,
       float scale, int Ktot, int ldc,
       size_t aB, size_t bB, size_t cB, int am, int cm, int guard, int qkv) {
    const bool skip = (guard && g_converged);
    if (skip && !cm) return;
    extern __shared__ char smem[];
    const int tid = threadIdx.x, lane = tid & 31, w = tid >> 5;

    if (!skip) {
        const uint32_t sb = smem_u32(smem);
        const int warp_m = (w & 1) * 64, warp_n = (w >> 1) * 64;

        const int z = blockIdx.z;
        const bf16 *Ah = Ah_, *Al = Al_;
        if (am) { int s = g_sel; Ah = g_sh[s]; Al = g_sl[s]; }
        Ah += (size_t)z * aB; Al += (size_t)z * aB;
        const bf16* Bh = Bh_ + (size_t)z * bB;
        const bf16* Bl = Bl_ + (size_t)z * bB;
        const float* Cold = nullptr;
        if (cm) {
            int s = g_sel ^ 1;
            Cf = g_sf[s]; Ch = g_sh[s]; Cl = g_sl[s];
            Cold = g_sf[s ^ 1] + (size_t)z * cB;
        }
        size_t nrow0 = (size_t)blockIdx.x * 128;
        int n0 = blockIdx.x * 128;
        if (qkv) {
            const int nw = HD * HD;
            int wi = blockIdx.x >> 2, bxl = blockIdx.x & 3;
            Bh = g_wh + wi * nw; Bl = g_wl + wi * nw;
            bias = (wi == 0) ? bias : (wi == 1) ? bias_k : bias_v;
            if (wi == 0)      { Cf = g_sf[0]; Ch = g_sh[0]; Cl = g_sl[0]; }
            else if (wi == 1) { Cf = g_tmpf;  Ch = g_kh;    Cl = g_kl;    }
            else              { Cf = g_scores; Ch = nullptr; Cl = nullptr; }
            nrow0 = (size_t)bxl * 128; n0 = bxl * 128;
        }
        if (Cf) Cf += (size_t)z * cB;
        if (Ch) { Ch += (size_t)z * cB; Cl += (size_t)z * cB; }

        const size_t row0 = (size_t)blockIdx.y * 128;

        uint32_t offA[4], offB[4];
#pragma unroll
        for (int mt = 0; mt < 4; mt++)
            offA[mt] = (uint32_t)(warp_m + mt * 16 + (lane & 7) + 8 * ((lane >> 3) & 1)) * 80
                     + (uint32_t)(lane >> 4) * 16;
#pragma unroll
        for (int p = 0; p < 4; p++)
            offB[p] = (uint32_t)(warp_n + p * 16 + (lane & 7) + 8 * (lane >> 4)) * 80
                    + (uint32_t)((lane >> 3) & 1) * 16;

        float acc[4][8][4];
#pragma unroll
        for (int mt = 0; mt < 4; mt++)
#pragma unroll
            for (int nt = 0; nt < 8; nt++)
#pragma unroll
                for (int i = 0; i < 4; i++) acc[mt][nt][i] = 0.0f;

        const int nch = Ktot >> 5;
        cpa_tile(sb,          Ah, row0,  0, Ktot, tid);
        cpa_tile(sb + TB,     Al, row0,  0, Ktot, tid);
        cpa_tile(sb + 2 * TB, Bh, nrow0, 0, Ktot, tid);
        cpa_tile(sb + 3 * TB, Bl, nrow0, 0, Ktot, tid);
        asm volatile("cp.async.commit_group;");

        for (int c = 0; c < nch; c++) {
            if (c + 1 < nch) {
                uint32_t s2 = sb + ((c + 1) & 1) * STG;
                int k0 = (c + 1) << 5;
                cpa_tile(s2,          Ah, row0,  k0, Ktot, tid);
                cpa_tile(s2 + TB,     Al, row0,  k0, Ktot, tid);
                cpa_tile(s2 + 2 * TB, Bh, nrow0, k0, Ktot, tid);
                cpa_tile(s2 + 3 * TB, Bl, nrow0, k0, Ktot, tid);
                asm volatile("cp.async.commit_group;");
                asm volatile("cp.async.wait_group 1;");
            } else {
                asm volatile("cp.async.wait_group 0;");
            }
            __syncthreads();

            const uint32_t ss = sb + (c & 1) * STG;
#pragma unroll
            for (int k16 = 0; k16 < 2; k16++) {
                const uint32_t kof = k16 * 32;
                uint32_t ah[4][4], al[4][4], bh[4][4], bl[4][4];
#pragma unroll
                for (int mt = 0; mt < 4; mt++) {
                    ldsm4(ah[mt], ss + offA[mt] + kof);
                    ldsm4(al[mt], ss + TB + offA[mt] + kof);
                }
#pragma unroll
                for (int p = 0; p < 4; p++) {
                    ldsm4(bh[p], ss + 2 * TB + offB[p] + kof);
                    ldsm4(bl[p], ss + 3 * TB + offB[p] + kof);
                }
#pragma unroll
                for (int p = 0; p < 4; p++) {
#pragma unroll
                    for (int sub = 0; sub < 2; sub++) {
                        const uint32_t* pbh = &bh[p][sub * 2];
                        const uint32_t* pbl = &bl[p][sub * 2];
                        int nt = p * 2 + sub;
#pragma unroll
                        for (int mt = 0; mt < 4; mt++) {
                            mma16816(acc[mt][nt], ah[mt], pbh);
                            mma16816(acc[mt][nt], ah[mt], pbl);
                            mma16816(acc[mt][nt], al[mt], pbh);
                        }
                    }
                }
            }
            __syncthreads();
        }

        // epilogue (+ fused Frobenius-delta partials when writing state)
        float sd = 0.0f, sn = 0.0f;
        const int cr = lane >> 2, cc = (lane & 3) * 2;
#pragma unroll
        for (int mt = 0; mt < 4; mt++) {
#pragma unroll
            for (int nt = 0; nt < 8; nt++) {
#pragma unroll
                for (int half = 0; half < 2; half++) {
                    int row = warp_m + mt * 16 + cr + half * 8;
                    int col = warp_n + nt * 8 + cc;
                    float vx = acc[mt][nt][half * 2 + 0] * scale;
                    float vy = acc[mt][nt][half * 2 + 1] * scale;
                    int gc = n0 + col;
                    if (bias) { vx += __ldg(bias + gc); vy += __ldg(bias + gc + 1); }
                    size_t ci = (row0 + row) * (size_t)ldc + gc;
                    if (Cf) { float2 o; o.x = vx; o.y = vy; *(float2*)(Cf + ci) = o; }
                    if (Cold) {
                        float2 ov = *(const float2*)(Cold + ci);
                        float dx = vx - ov.x, dy = vy - ov.y;
                        sd += dx * dx + dy * dy;
                        sn += ov.x * ov.x + ov.y * ov.y;
                    }
                    if (Ch) {
                        __nv_bfloat162 hv, lv;
                        split2(vx, hv.x, lv.x);
                        split2(vy, hv.y, lv.y);
                        *(__nv_bfloat162*)(Ch + ci) = hv;
                        *(__nv_bfloat162*)(Cl + ci) = lv;
                    }
                }
            }
        }
        if (Cold) {
#pragma unroll
            for (int o = 16; o; o >>= 1) {
                sd += __shfl_xor_sync(0xffffffffu, sd, o);
                sn += __shfl_xor_sync(0xffffffffu, sn, o);
            }
            float* rbuf = (float*)smem;
            __syncthreads();
            if (lane == 0) { rbuf[w] = sd; rbuf[4 + w] = sn; }
            __syncthreads();
            if (tid == 0) {
                float t1 = 0.0f, t2 = 0.0f;
#pragma unroll
                for (int i = 0; i < 4; i++) { t1 += rbuf[i]; t2 += rbuf[4 + i]; }
                atomicAdd(&g_sumd, t1);
                atomicAdd(&g_sumn, t2);
            }
        }
    }

    // device-side finalize: last AV CTA computes delta, updates control state
    if (cm && tid == 0) {
        __threadfence();
        int ntiles = (int)(gridDim.x * gridDim.y * gridDim.z);
        int done = atomicAdd(&g_ctr, 1);
        if (done == ntiles - 1) {
            if (!g_converged) {
                float sumd = atomicAdd(&g_sumd, 0.0f);
                float sumn = atomicAdd(&g_sumn, 0.0f);
                float delta = sqrtf(sumd) / (sqrtf(sumn) + 1e-8f);
                g_iters += 1;
                if (delta < 1e-4f) g_converged = 1;
                g_sel ^= 1;
            }
            g_sumd = 0.0f; g_sumn = 0.0f;
            g_ctr = 0;
            __threadfence();
        }
    }
}

// ---- launch ----
extern "C" void kernel_launch(void* const* d_in, const int* in_sizes, int n_in,
                              void* d_out, int out_size) {
    const float* x  = (const float*)d_in[0];
    const float* Wq = (const float*)d_in[1];
    const float* bq = (const float*)d_in[2];
    const float* Wk = (const float*)d_in[3];
    const float* bk = (const float*)d_in[4];
    const float* Wv = (const float*)d_in[5];
    const float* bv = (const float*)d_in[6];
    const float* Wo = (const float*)d_in[7];
    const float* bo = (const float*)d_in[8];
    float* out = (float*)d_out;

    void* pv;
    cudaGetSymbolAddress(&pv, g_xh);   bf16* xh = (bf16*)pv;
    cudaGetSymbolAddress(&pv, g_xl);   bf16* xl = (bf16*)pv;
    cudaGetSymbolAddress(&pv, g_kh);   bf16* kh = (bf16*)pv;
    cudaGetSymbolAddress(&pv, g_kl);   bf16* kl = (bf16*)pv;
    cudaGetSymbolAddress(&pv, g_kth);  bf16* kth = (bf16*)pv;
    cudaGetSymbolAddress(&pv, g_ktl);  bf16* ktl = (bf16*)pv;
    cudaGetSymbolAddress(&pv, g_vth);  bf16* vth = (bf16*)pv;
    cudaGetSymbolAddress(&pv, g_vtl);  bf16* vtl = (bf16*)pv;
    cudaGetSymbolAddress(&pv, g_ath);  bf16* ath = (bf16*)pv;
    cudaGetSymbolAddress(&pv, g_atl);  bf16* atl = (bf16*)pv;
    cudaGetSymbolAddress(&pv, g_wh);   bf16* wh = (bf16*)pv;
    cudaGetSymbolAddress(&pv, g_wl);   bf16* wl = (bf16*)pv;
    cudaGetSymbolAddress(&pv, g_tmpf); float* tmpf = (float*)pv;
    cudaGetSymbolAddress(&pv, g_scores); float* sc = (float*)pv;
    cudaGetSymbolAddress(&pv, g_ph);   bf16* ph = (bf16*)pv;
    cudaGetSymbolAddress(&pv, g_pl);   bf16* pl = (bf16*)pv;

    cudaFuncSetAttribute(k_gemm, cudaFuncAttributeMaxDynamicSharedMemorySize, SMEM_BYTES);

    const int nw = HD * HD;
    const dim3 gQKV(12, 64, 1);   // fused q/k/v projections: 8192 x 1536
    const dim3 gP(4, 64, 1);
    const dim3 gS(16, 16, 4);
    const dim3 gV(4, 16, 4);
    const dim3 gT2(16, 64, 8);    // merged K+V transpose
    const dim3 bT(32, 8);
    const size_t aS = (size_t)SQ * HD, cS = (size_t)SQ * SQ;

    k_init<<<1, 1>>>();
    k_cvt_all<<<BSH / 1024 + 4 * (nw / 1024), 256>>>(x, Wq, Wk, Wv, Wo);

    // fused QKV: q -> state0 (f+h+l)+bq, k -> tmpf+kh/kl+bk, v -> scores scratch+bv
    k_gemm<<<gQKV, 128, SMEM_BYTES>>>(xh, xl, nullptr, nullptr,
                                      nullptr, nullptr, nullptr,
                                      bq, bk, bv, 1.0f,
                                      HD, HD, 0, 0, 0, 0, 0, 0, 1);
    // merged transpose-convert of K (from tmpf) and V (from scores scratch)
    k_tcvt2<<<gT2, bT>>>(tmpf, sc);

    for (int it = 0; it < 5; it++) {
        k_gemm<<<gS, 128, SMEM_BYTES>>>(nullptr, nullptr, kh, kl, sc, nullptr, nullptr,
                                        nullptr, nullptr, nullptr, KSCALE,
                                        HD, SQ, aS, aS, cS, 1, 0, 1, 0);
        k_softmax<<<NB * SQ, 256>>>(1);
        // AV with on-device finalize (cm=1)
        k_gemm<<<gV, 128, SMEM_BYTES>>>(ph, pl, kth, ktl, nullptr, nullptr, nullptr,
                                        nullptr, nullptr, nullptr, 1.0f,
                                        SQ, HD, cS, aS, aS, 0, 1, 1, 0);
    }

    // readout vs values, then output projection
    k_gemm<<<gS, 128, SMEM_BYTES>>>(nullptr, nullptr, kh, kl, sc, nullptr, nullptr,
                                    nullptr, nullptr, nullptr, KSCALE,
                                    HD, SQ, aS, aS, cS, 1, 0, 0, 0);
    k_softmax<<<NB * SQ, 256>>>(0);
    k_gemm<<<gV, 128, SMEM_BYTES>>>(ph, pl, vth, vtl, nullptr, ath, atl,
                                    nullptr, nullptr, nullptr, 1.0f,
                                    SQ, HD, cS, aS, aS, 0, 0, 0, 0);
    k_gemm<<<gP, 128, SMEM_BYTES>>>(ath, atl, wh + 3 * nw, wl + 3 * nw, out, nullptr, nullptr,
                                    bo, nullptr, nullptr, 1.0f,
                                    HD, HD, 0, 0, 0, 0, 0, 0, 0);

    if (out_size > BSH) k_tail<<<1, 1>>>(out, out_size - BSH);
}